// round 13
// baseline (speedup 1.0000x reference)
#include <cuda_runtime.h>
#include <cuda_fp16.h>
#include <math_constants.h>

// GAT autoencoder, CSR-gather formulation. h matrix stored fp16 (gather
// operand only; all accumulation + outputs fp32).
// Layers: 64->64 relu, 64->32 [h out], relu, 32->64 relu, 64->64 [out].
// Outputs concatenated: out [N*64] then h [N*32].

#define MAXN 50000
#define MAXE 800000
#define MAXET (MAXE + MAXN)
#define MAXBLK 64
#define STASH 80  // per-warp smem logit stash (deg > STASH falls back to g_e)

// ---------------- scratch ----------------
__device__ __align__(16) float g_featA[MAXN * 64];
__device__ __align__(16) float g_featB[MAXN * 64];
__device__ __align__(16) __half g_h[MAXN * 64];
__device__ float g_ssrc[MAXN];
__device__ float g_sdst[MAXN];
__device__ float g_e[MAXET];  // fallback only (deg > STASH)
__device__ int g_src[MAXET];
__device__ int g_dst[MAXET];
__device__ int g_adj[MAXET];
__device__ int g_roff[MAXN + 1];
__device__ int g_cnt[MAXN];
__device__ int g_cur[MAXN];
__device__ int g_bt[MAXBLK];
__device__ int g_boff[MAXBLK];
__device__ int g_is64;

__device__ __forceinline__ const float* pick_src(int sel, const float* ext) {
    if (sel == 1) return g_featA;
    if (sel == 2) return g_featB;
    return ext;
}
__device__ __forceinline__ float* pick_dst(int sel) {
    if (sel == 1) return g_featA;
    if (sel == 2) return g_featB;
    return nullptr;
}

// ---------------- graph prep ----------------

// parallel dtype detect: int64 little-endian ids < 2^31 => odd words all 0
__global__ void k_detect(const unsigned int* __restrict__ w, int nelem) {
    __shared__ int bad;
    if (threadIdx.x == 0) bad = 0;
    __syncthreads();
    int idx = 2 * (int)threadIdx.x + 1;
    if (idx < 2 * nelem && idx < 256 && w[idx] != 0) atomicOr(&bad, 1);
    __syncthreads();
    if (threadIdx.x == 0) g_is64 = !bad;
}

__global__ void k_zero(int n) {
    int i = blockIdx.x * 256 + threadIdx.x;
    if (i < n) g_cnt[i] = 0;
}

// convert + degree histogram fused
__global__ void k_convert(const void* __restrict__ ei, int eraw, int n) {
    int i = blockIdx.x * 256 + threadIdx.x;
    int etot = eraw + n;
    if (i >= etot) return;
    int s, d;
    if (i < eraw) {
        if (g_is64) {
            const long long* p = (const long long*)ei;
            s = (int)p[i];
            d = (int)p[eraw + i];
        } else {
            const int* p = (const int*)ei;
            s = p[i];
            d = p[eraw + i];
        }
        s = s < 0 ? 0 : (s >= n ? n - 1 : s);
        d = d < 0 ? 0 : (d >= n ? n - 1 : d);
    } else {
        s = d = i - eraw;
    }
    g_src[i] = s;
    g_dst[i] = d;
    atomicAdd(&g_cnt[d], 1);
}

// --- two-level exclusive scan of g_cnt ---
__global__ void k_scan_bt(int n) {
    int base = blockIdx.x * 1024;
    int i0 = base + threadIdx.x * 4;
    int t = 0;
#pragma unroll
    for (int c = 0; c < 4; c++) t += (i0 + c < n) ? g_cnt[i0 + c] : 0;
    int lane = threadIdx.x & 31, wid = threadIdx.x >> 5;
#pragma unroll
    for (int off = 16; off; off >>= 1) t += __shfl_xor_sync(~0u, t, off);
    __shared__ int ws[8];
    if (lane == 0) ws[wid] = t;
    __syncthreads();
    if (threadIdx.x == 0) {
        int s = 0;
#pragma unroll
        for (int w = 0; w < 8; w++) s += ws[w];
        g_bt[blockIdx.x] = s;
    }
}

__global__ void k_scan_mid(int nblk, int n) {
    int lane = threadIdx.x;
    int carry = 0;
    for (int base = 0; base < nblk; base += 32) {
        int i = base + lane;
        int v = (i < nblk) ? g_bt[i] : 0;
        int incl = v;
#pragma unroll
        for (int off = 1; off < 32; off <<= 1) {
            int t = __shfl_up_sync(~0u, incl, off);
            if (lane >= off) incl += t;
        }
        if (i < nblk) g_boff[i] = carry + incl - v;
        carry += __shfl_sync(~0u, incl, 31);
    }
    if (lane == 0) g_roff[n] = carry;
}

__global__ void k_scan_wr(int n) {
    int base = blockIdx.x * 1024;
    int i0 = base + threadIdx.x * 4;
    int v[4], tsum = 0;
#pragma unroll
    for (int c = 0; c < 4; c++) {
        v[c] = (i0 + c < n) ? g_cnt[i0 + c] : 0;
        tsum += v[c];
    }
    int lane = threadIdx.x & 31, wid = threadIdx.x >> 5;
    int incl = tsum;
#pragma unroll
    for (int off = 1; off < 32; off <<= 1) {
        int t = __shfl_up_sync(~0u, incl, off);
        if (lane >= off) incl += t;
    }
    __shared__ int ws[8];
    if (lane == 31) ws[wid] = incl;
    __syncthreads();
    int woff = 0;
    for (int w = 0; w < wid; w++) woff += ws[w];
    int ex = g_boff[blockIdx.x] + woff + incl - tsum;
#pragma unroll
    for (int c = 0; c < 4; c++) {
        if (i0 + c < n) {
            g_roff[i0 + c] = ex;
            g_cur[i0 + c] = ex;
            ex += v[c];
        }
    }
}

__global__ void k_scatter(int etot) {
    int i = blockIdx.x * 256 + threadIdx.x;
    if (i >= etot) return;
    int pos = atomicAdd(&g_cur[g_dst[i]], 1);
    g_adj[pos] = g_src[i];
}

// ---------------- fused gemm + attention scores ----------------
// fp32 compute; h written as fp16 (gather operand). Scores from fp32 accs.
template <int DI, int DO>
__global__ void k_gemm_sc(int xsel, const float* __restrict__ xext,
                          const float* __restrict__ W,
                          const float* __restrict__ as_,
                          const float* __restrict__ ad_, int n) {
    __shared__ float Ws[DI * DO];
    for (int i = threadIdx.x; i < DI * DO; i += blockDim.x) Ws[i] = W[i];
    __syncthreads();
    int row = (blockIdx.x * blockDim.x + threadIdx.x) >> 5;
    int lane = threadIdx.x & 31;
    if (row >= n) return;
    const float* x = pick_src(xsel, xext) + row * DI;
    float acc0 = 0.f, acc1 = 0.f;
#pragma unroll
    for (int k0 = 0; k0 < DI; k0 += 32) {
        float xv = x[k0 + lane];
#pragma unroll
        for (int kk = 0; kk < 32; kk++) {
            float xk = __shfl_sync(0xFFFFFFFFu, xv, kk);
            acc0 = fmaf(xk, Ws[(k0 + kk) * DO + lane], acc0);
            if (DO == 64) acc1 = fmaf(xk, Ws[(k0 + kk) * DO + lane + 32], acc1);
        }
    }
    g_h[row * DO + lane] = __float2half(acc0);
    if (DO == 64) g_h[row * DO + lane + 32] = __float2half(acc1);
    float ss = acc0 * __ldg(as_ + lane);
    float sd = acc0 * __ldg(ad_ + lane);
    if (DO == 64) {
        ss = fmaf(acc1, __ldg(as_ + lane + 32), ss);
        sd = fmaf(acc1, __ldg(ad_ + lane + 32), sd);
    }
#pragma unroll
    for (int off = 16; off; off >>= 1) {
        ss += __shfl_xor_sync(0xFFFFFFFFu, ss, off);
        sd += __shfl_xor_sync(0xFFFFFFFFu, sd, off);
    }
    if (lane == 0) {
        g_ssrc[row] = ss;
        g_sdst[row] = sd;
    }
}

// ---------------- fused softmax + aggregation ----------------
// warp per dst node. Pass 1: logits from adj+ssrc, smem stash, warp max.
// Pass 2: two half-warps, alternating edges; h rows read as fp16.
template <int DO>
__global__ void k_gather(const float* __restrict__ b, int featsel,
                         float* __restrict__ raw, int n) {
    const int C = DO / 16;  // 4 (DO=64) or 2 (DO=32) cols per lane
    __shared__ float es[16][STASH];
    int wslot = threadIdx.x >> 5;
    int d = (blockIdx.x * blockDim.x + threadIdx.x) >> 5;
    int lane = threadIdx.x & 31;
    int half = lane >> 4, l16 = lane & 15;
    if (d >= n) return;
    int r0 = __ldg(&g_roff[d]);
    int r1 = __ldg(&g_roff[d + 1]);
    float sd = g_sdst[d];

    // pass 1
    float m = -CUDART_INF_F;
    for (int j = r0 + lane; j < r1; j += 32) {
        int s = __ldg(&g_adj[j]);
        float e = __ldg(&g_ssrc[s]) + sd;
        e = e > 0.f ? e : 0.2f * e;
        int k = j - r0;
        if (k < STASH) es[wslot][k] = e;
        else g_e[j] = e;
        m = fmaxf(m, e);
    }
#pragma unroll
    for (int off = 16; off; off >>= 1)
        m = fmaxf(m, __shfl_xor_sync(0xFFFFFFFFu, m, off));
    __syncwarp();

    // pass 2
    float den = 0.f;
    float acc[C];
#pragma unroll
    for (int c = 0; c < C; c++) acc[c] = 0.f;
    for (int j = r0 + half; j < r1; j += 2) {
        int k = j - r0;
        float e = (k < STASH) ? es[wslot][k] : g_e[j];
        int s = __ldg(&g_adj[j]);
        float ex = __expf(e - m);
        den += ex;
        float hv[C];
        if (C == 4) {
            uint2 t = __ldg(reinterpret_cast<const uint2*>(g_h + s * DO) + l16);
            float2 p0 = __half22float2(*reinterpret_cast<__half2*>(&t.x));
            float2 p1 = __half22float2(*reinterpret_cast<__half2*>(&t.y));
            hv[0] = p0.x; hv[1] = p0.y; hv[2] = p1.x; hv[3] = p1.y;
        } else {
            unsigned int t = __ldg(reinterpret_cast<const unsigned int*>(g_h + s * DO) + l16);
            float2 p = __half22float2(*reinterpret_cast<__half2*>(&t));
            hv[0] = p.x; hv[1] = p.y;
        }
#pragma unroll
        for (int c = 0; c < C; c++) acc[c] = fmaf(ex, hv[c], acc[c]);
    }
    // merge the two halves
    den += __shfl_xor_sync(0xFFFFFFFFu, den, 16);
#pragma unroll
    for (int c = 0; c < C; c++) acc[c] += __shfl_xor_sync(0xFFFFFFFFu, acc[c], 16);

    if (half == 0) {
        float inv = 1.f / (den + 1e-16f);
        float v[C];
#pragma unroll
        for (int c = 0; c < C; c++)
            v[c] = acc[c] * inv + __ldg(b + l16 * C + c);
        float* feat = pick_dst(featsel);
        if (raw) {
            if (C == 4)
                reinterpret_cast<float4*>(raw + d * DO)[l16] =
                    make_float4(v[0], v[1], v[2], v[3]);
            else
                reinterpret_cast<float2*>(raw + d * DO)[l16] =
                    make_float2(v[0], v[1]);
        }
        if (feat) {
#pragma unroll
            for (int c = 0; c < C; c++) v[c] = v[c] > 0.f ? v[c] : 0.f;
            if (C == 4)
                reinterpret_cast<float4*>(feat + d * DO)[l16] =
                    make_float4(v[0], v[1], v[2], v[3]);
            else
                reinterpret_cast<float2*>(feat + d * DO)[l16] =
                    make_float2(v[0], v[1]);
        }
    }
}

// ---------------- launch ----------------
extern "C" void kernel_launch(void* const* d_in, const int* in_sizes, int n_in,
                              void* d_out, int out_size) {
    const float* x = (const float*)d_in[0];
    const void* ei = d_in[1];
    const float* w1 = (const float*)d_in[2];
    const float* as1 = (const float*)d_in[3];
    const float* ad1 = (const float*)d_in[4];
    const float* b1 = (const float*)d_in[5];
    const float* w2 = (const float*)d_in[6];
    const float* as2 = (const float*)d_in[7];
    const float* ad2 = (const float*)d_in[8];
    const float* b2 = (const float*)d_in[9];
    const float* w3 = (const float*)d_in[10];
    const float* as3 = (const float*)d_in[11];
    const float* ad3 = (const float*)d_in[12];
    const float* b3 = (const float*)d_in[13];
    const float* w4 = (const float*)d_in[14];
    const float* as4 = (const float*)d_in[15];
    const float* ad4 = (const float*)d_in[16];
    const float* b4 = (const float*)d_in[17];

    int n = in_sizes[0] / 64;
    int eraw = in_sizes[1] / 2;
    int etot = eraw + n;

    float* out_sec = (float*)d_out;         // [n*64]
    float* h_sec = (float*)d_out + n * 64;  // [n*32]

    int nbE = (etot + 255) / 256;
    int nbN = (n + 255) / 256;
    int nbW = (n * 32 + 511) / 512;
    int nblk = (n + 1023) / 1024;

    // graph prep (once per call)
    k_detect<<<1, 128>>>((const unsigned int*)ei, in_sizes[1]);
    k_zero<<<nbN, 256>>>(n);
    k_convert<<<nbE, 256>>>(ei, eraw, n);
    k_scan_bt<<<nblk, 256>>>(n);
    k_scan_mid<<<1, 32>>>(nblk, n);
    k_scan_wr<<<nblk, 256>>>(n);
    k_scatter<<<nbE, 256>>>(etot);

    // layer 1: x 64->64, relu -> featA
    k_gemm_sc<64, 64><<<nbW, 512>>>(0, x, w1, as1, ad1, n);
    k_gather<64><<<nbW, 512>>>(b1, 1, nullptr, n);

    // layer 2: featA 64->32, raw h -> d_out, relu -> featB
    k_gemm_sc<64, 32><<<nbW, 512>>>(1, nullptr, w2, as2, ad2, n);
    k_gather<32><<<nbW, 512>>>(b2, 2, h_sec, n);

    // layer 3: featB 32->64, relu -> featA
    k_gemm_sc<32, 64><<<nbW, 512>>>(2, nullptr, w3, as3, ad3, n);
    k_gather<64><<<nbW, 512>>>(b3, 1, nullptr, n);

    // layer 4: featA 64->64, raw -> d_out
    k_gemm_sc<64, 64><<<nbW, 512>>>(1, nullptr, w4, as4, ad4, n);
    k_gather<64><<<nbW, 512>>>(b4, 0, out_sec, n);
}